// round 2
// baseline (speedup 1.0000x reference)
#include <cuda_runtime.h>
#include <math.h>

#define B_ 2
#define N_ 4096
#define M_ 4096
#define D_ 512
#define H_ 8
#define P_ 64

// Scratch: projected Q/K/V in [B, H, seq, P] layout (16 MB each)
__device__ float g_Q[(size_t)B_ * H_ * N_ * P_];
__device__ float g_K[(size_t)B_ * H_ * M_ * P_];
__device__ float g_V[(size_t)B_ * H_ * M_ * P_];

// ---------------------------------------------------------------------------
// Projection GEMM: out[b,h,seq,p] = X[b,seq,:] @ W[:, h*P+p] + bias[h*P+p]
// BM=64, BN=64, BK=16, 256 threads, 4x4 register tile per thread.
// blockIdx.z selects which of the three projections (Q/K/V).
// ---------------------------------------------------------------------------
__global__ __launch_bounds__(256) void proj_kernel(
    const float* __restrict__ xq, const float* __restrict__ xk, const float* __restrict__ xv,
    const float* __restrict__ Wq, const float* __restrict__ Wk, const float* __restrict__ Wv,
    const float* __restrict__ bq, const float* __restrict__ bk, const float* __restrict__ bv)
{
    const float* X; const float* W; const float* bias; float* out;
    if (blockIdx.z == 0)      { X = xq; W = Wq; bias = bq; out = g_Q; }
    else if (blockIdx.z == 1) { X = xk; W = Wk; bias = bk; out = g_K; }
    else                      { X = xv; W = Wv; bias = bv; out = g_V; }

    __shared__ float As[16][68];   // A tile stored transposed: As[k][m]
    __shared__ float Bs[16][68];   // B tile: Bs[k][n]

    const int tid = threadIdx.x;
    const int ty = tid >> 4, tx = tid & 15;
    const int r0 = blockIdx.y * 64;      // row tile (over B*N = 8192)
    const int c0 = blockIdx.x * 64;      // col tile (over D = 512) == one head

    const int arow = tid >> 2, acg = tid & 3;     // A load mapping
    const int brow = tid >> 4, bcg = tid & 15;    // B load mapping

    float acc[4][4] = {};

    for (int k0 = 0; k0 < D_; k0 += 16) {
        float4 av  = *(const float4*)&X[(r0 + arow) * D_ + k0 + acg * 4];
        float4 bv4 = *(const float4*)&W[(k0 + brow) * D_ + c0 + bcg * 4];
        __syncthreads();
        As[acg * 4 + 0][arow] = av.x;
        As[acg * 4 + 1][arow] = av.y;
        As[acg * 4 + 2][arow] = av.z;
        As[acg * 4 + 3][arow] = av.w;
        *(float4*)&Bs[brow][bcg * 4] = bv4;
        __syncthreads();
        #pragma unroll
        for (int k = 0; k < 16; k++) {
            float4 a = *(const float4*)&As[k][ty * 4];
            float4 b = *(const float4*)&Bs[k][tx * 4];
            acc[0][0] += a.x * b.x; acc[0][1] += a.x * b.y; acc[0][2] += a.x * b.z; acc[0][3] += a.x * b.w;
            acc[1][0] += a.y * b.x; acc[1][1] += a.y * b.y; acc[1][2] += a.y * b.z; acc[1][3] += a.y * b.w;
            acc[2][0] += a.z * b.x; acc[2][1] += a.z * b.y; acc[2][2] += a.z * b.z; acc[2][3] += a.z * b.w;
            acc[3][0] += a.w * b.x; acc[3][1] += a.w * b.y; acc[3][2] += a.w * b.z; acc[3][3] += a.w * b.w;
        }
    }

    const int h = c0 >> 6;   // one 64-col tile == one head
    float4 bb = *(const float4*)&bias[c0 + tx * 4];
    #pragma unroll
    for (int i = 0; i < 4; i++) {
        int r = r0 + ty * 4 + i;
        int b = r >> 12;            // / N_
        int n = r & (N_ - 1);       // % N_
        float4 o;
        o.x = acc[i][0] + bb.x;
        o.y = acc[i][1] + bb.y;
        o.z = acc[i][2] + bb.z;
        o.w = acc[i][3] + bb.w;
        *(float4*)&out[(((b * H_ + h) * N_) + n) * P_ + tx * 4] = o;
    }
}

// ---------------------------------------------------------------------------
// Flash attention: one CTA per (b, h, 64-row query tile).
// 64-row KV tiles; S (64x64) lives in registers (4x4 per thread, 16x16 grid);
// softmax row reductions via half-warp shuffles (tx spans lanes 0..15);
// P is written back into the K smem buffer for the PV matmul.
// smem: Qs 64x64 | Ks 64x65 (reused as P) | Vs 64x64  = 49408 bytes.
// ---------------------------------------------------------------------------
__global__ __launch_bounds__(256) void attn_kernel(float* __restrict__ out)
{
    extern __shared__ float smem[];
    float* Qs = smem;                 // [64][64]
    float* Ks = smem + 64 * 64;       // [64][65]  (reused as P)
    float* Vs = Ks + 64 * 65;         // [64][64]

    const int tid = threadIdx.x;
    const int ty = tid >> 4, tx = tid & 15;
    const int b = blockIdx.z, h = blockIdx.y;
    const int n0 = blockIdx.x * 64;

    const float* Qg = g_Q + ((b * H_ + h) * N_ + n0) * P_;
    const float* Kg = g_K + (b * H_ + h) * (M_ * P_);
    const float* Vg = g_V + (b * H_ + h) * (M_ * P_);

    // Load Q tile (64x64 floats, float4 per thread x4)
    #pragma unroll
    for (int i = 0; i < 4; i++) {
        int fi = i * 256 + tid;
        int row = fi >> 4, cg = fi & 15;
        *(float4*)&Qs[row * 64 + cg * 4] = *(const float4*)&Qg[row * P_ + cg * 4];
    }

    float m_i[4], l_i[4], o[4][4];
    #pragma unroll
    for (int r = 0; r < 4; r++) {
        m_i[r] = -INFINITY; l_i[r] = 0.f;
        #pragma unroll
        for (int c = 0; c < 4; c++) o[r][c] = 0.f;
    }

    for (int t = 0; t < M_ / 64; t++) {
        __syncthreads();   // previous PV reads done before overwriting Ks/Vs
        const float* Kt = Kg + t * 64 * P_;
        const float* Vt = Vg + t * 64 * P_;
        #pragma unroll
        for (int i = 0; i < 4; i++) {
            int fi = i * 256 + tid;
            int row = fi >> 4, cg = fi & 15;
            float4 kv = *(const float4*)&Kt[row * P_ + cg * 4];
            Ks[row * 65 + cg * 4 + 0] = kv.x;
            Ks[row * 65 + cg * 4 + 1] = kv.y;
            Ks[row * 65 + cg * 4 + 2] = kv.z;
            Ks[row * 65 + cg * 4 + 3] = kv.w;
            *(float4*)&Vs[row * 64 + cg * 4] = *(const float4*)&Vt[row * P_ + cg * 4];
        }
        __syncthreads();

        // S = Q @ K^T  (register 4x4 fragment per thread)
        float s[4][4] = {};
        #pragma unroll 8
        for (int p = 0; p < 64; p++) {
            float q[4], k[4];
            #pragma unroll
            for (int r = 0; r < 4; r++) q[r] = Qs[(ty * 4 + r) * 64 + p];
            #pragma unroll
            for (int c = 0; c < 4; c++) k[c] = Ks[(tx * 4 + c) * 65 + p];
            #pragma unroll
            for (int r = 0; r < 4; r++)
                #pragma unroll
                for (int c = 0; c < 4; c++)
                    s[r][c] += q[r] * k[c];
        }
        #pragma unroll
        for (int r = 0; r < 4; r++)
            #pragma unroll
            for (int c = 0; c < 4; c++)
                s[r][c] *= 0.125f;   // 1/sqrt(P), P=64

        // Online softmax: row max / sum across tx (lanes 0..15 of half-warp)
        float rmax[4];
        #pragma unroll
        for (int r = 0; r < 4; r++)
            rmax[r] = fmaxf(fmaxf(s[r][0], s[r][1]), fmaxf(s[r][2], s[r][3]));
        #pragma unroll
        for (int off = 8; off > 0; off >>= 1)
            #pragma unroll
            for (int r = 0; r < 4; r++)
                rmax[r] = fmaxf(rmax[r], __shfl_xor_sync(0xffffffffu, rmax[r], off));

        float alpha[4];
        #pragma unroll
        for (int r = 0; r < 4; r++) {
            float nm = fmaxf(m_i[r], rmax[r]);
            alpha[r] = __expf(m_i[r] - nm);
            m_i[r] = nm;
        }

        float rsum[4] = {0.f, 0.f, 0.f, 0.f};
        #pragma unroll
        for (int r = 0; r < 4; r++)
            #pragma unroll
            for (int c = 0; c < 4; c++) {
                s[r][c] = __expf(s[r][c] - m_i[r]);
                rsum[r] += s[r][c];
            }
        #pragma unroll
        for (int off = 8; off > 0; off >>= 1)
            #pragma unroll
            for (int r = 0; r < 4; r++)
                rsum[r] += __shfl_xor_sync(0xffffffffu, rsum[r], off);

        #pragma unroll
        for (int r = 0; r < 4; r++) {
            l_i[r] = l_i[r] * alpha[r] + rsum[r];
            #pragma unroll
            for (int c = 0; c < 4; c++) o[r][c] *= alpha[r];
        }

        // Stage P into the (now dead) K buffer
        __syncthreads();
        #pragma unroll
        for (int r = 0; r < 4; r++)
            #pragma unroll
            for (int c = 0; c < 4; c++)
                Ks[(ty * 4 + r) * 65 + tx * 4 + c] = s[r][c];
        __syncthreads();

        // O += P @ V
        #pragma unroll 8
        for (int j = 0; j < 64; j++) {
            float pr[4];
            #pragma unroll
            for (int r = 0; r < 4; r++) pr[r] = Ks[(ty * 4 + r) * 65 + j];
            float4 v4 = *(const float4*)&Vs[j * 64 + tx * 4];
            #pragma unroll
            for (int r = 0; r < 4; r++) {
                o[r][0] += pr[r] * v4.x;
                o[r][1] += pr[r] * v4.y;
                o[r][2] += pr[r] * v4.z;
                o[r][3] += pr[r] * v4.w;
            }
        }
    }

    // Epilogue: normalize and store to [B, N, D] with d = h*64 + col
    #pragma unroll
    for (int r = 0; r < 4; r++) {
        float inv = 1.f / l_i[r];
        int n = n0 + ty * 4 + r;
        float4 res;
        res.x = o[r][0] * inv;
        res.y = o[r][1] * inv;
        res.z = o[r][2] * inv;
        res.w = o[r][3] * inv;
        *(float4*)&out[((size_t)(b * N_ + n)) * D_ + h * 64 + tx * 4] = res;
    }
}

// ---------------------------------------------------------------------------
extern "C" void kernel_launch(void* const* d_in, const int* in_sizes, int n_in,
                              void* d_out, int out_size)
{
    const float* xq = (const float*)d_in[0];
    const float* xk = (const float*)d_in[1];
    const float* xv = (const float*)d_in[2];
    const float* Wq = (const float*)d_in[3];
    const float* bq = (const float*)d_in[4];
    const float* Wk = (const float*)d_in[5];
    const float* bk = (const float*)d_in[6];
    const float* Wv = (const float*)d_in[7];
    const float* bv = (const float*)d_in[8];
    float* out = (float*)d_out;

    const int attn_smem = (64 * 64 + 64 * 65 + 64 * 64) * (int)sizeof(float);  // 49408
    cudaFuncSetAttribute(attn_kernel, cudaFuncAttributeMaxDynamicSharedMemorySize, attn_smem);

    // 3 projections via blockIdx.z
    proj_kernel<<<dim3(D_ / 64, (B_ * N_) / 64, 3), 256>>>(xq, xk, xv, Wq, Wk, Wv, bq, bk, bv);

    // Flash attention: (query tiles, heads, batch)
    attn_kernel<<<dim3(N_ / 64, H_, B_), 256, attn_smem>>>(out);
}

// round 4
// speedup vs baseline: 2.9429x; 2.9429x over previous
#include <cuda_runtime.h>
#include <math.h>
#include <stdint.h>

#define B_ 2
#define N_ 4096
#define M_ 4096
#define D_ 512
#define H_ 8
#define P_ 64

// Scratch: projected Q/K/V in [B, H, seq, P] layout (fp32)
__device__ float g_Q[(size_t)B_ * H_ * N_ * P_];
__device__ float g_K[(size_t)B_ * H_ * M_ * P_];
__device__ float g_V[(size_t)B_ * H_ * M_ * P_];

// round fp32 -> tf32 (rna), keep as fp32 bit pattern.
// NOTE: cvt.rna.tf32.f32 requires a b32 register destination ("=r"), not "=f".
__device__ __forceinline__ float tf32r(float x) {
    uint32_t r;
    asm("cvt.rna.tf32.f32 %0, %1;" : "=r"(r) : "f"(x));
    return __uint_as_float(r);
}

// D += A * B, m16n8k8 tf32. a[4], b[2] are tf32-formatted fp32 values.
__device__ __forceinline__ void mma8(float* c, const float* a, const float* b) {
    asm volatile(
        "mma.sync.aligned.m16n8k8.row.col.f32.tf32.tf32.f32 "
        "{%0,%1,%2,%3}, {%4,%5,%6,%7}, {%8,%9}, {%0,%1,%2,%3};"
        : "+f"(c[0]), "+f"(c[1]), "+f"(c[2]), "+f"(c[3])
        : "r"(__float_as_uint(a[0])), "r"(__float_as_uint(a[1])),
          "r"(__float_as_uint(a[2])), "r"(__float_as_uint(a[3])),
          "r"(__float_as_uint(b[0])), "r"(__float_as_uint(b[1])));
}

// ---------------------------------------------------------------------------
// Projection GEMM (tf32 MMA): out[b,h,seq,p] = X[b*seq,:] @ W[:,h*64+p] + bias
// BM=128, BN=64, BK=32. 256 threads = 8 warps; warp tile = 16 rows x 64 cols.
// ---------------------------------------------------------------------------
__global__ __launch_bounds__(256) void proj_kernel(
    const float* __restrict__ xq, const float* __restrict__ xk, const float* __restrict__ xv,
    const float* __restrict__ Wq, const float* __restrict__ Wk, const float* __restrict__ Wv,
    const float* __restrict__ bq, const float* __restrict__ bk, const float* __restrict__ bv)
{
    const float* X; const float* W; const float* bias; float* out;
    if (blockIdx.z == 0)      { X = xq; W = Wq; bias = bq; out = g_Q; }
    else if (blockIdx.z == 1) { X = xk; W = Wk; bias = bk; out = g_K; }
    else                      { X = xv; W = Wv; bias = bv; out = g_V; }

    __shared__ float Xs[128 * 36];   // A tile, stride 36 (A-frag conflict-free)
    __shared__ float Ws[32 * 72];    // B tile, stride 72 (B-frag conflict-free)

    const int tid = threadIdx.x;
    const int w = tid >> 5, lane = tid & 31;
    const int g = lane >> 2, t = lane & 3;
    const int r0 = blockIdx.y * 128;     // rows over B*N = 8192
    const int c0 = blockIdx.x * 64;      // cols over D = 512 (one head)

    float c[8][4];
    #pragma unroll
    for (int j = 0; j < 8; j++)
        #pragma unroll
        for (int e = 0; e < 4; e++) c[j][e] = 0.f;

    for (int k0 = 0; k0 < D_; k0 += 32) {
        __syncthreads();
        // X tile: 128x32 (1024 float4)
        #pragma unroll
        for (int i = 0; i < 4; i++) {
            int fi = i * 256 + tid;
            int row = fi >> 3, cg = fi & 7;
            float4 v = *(const float4*)&X[(r0 + row) * D_ + k0 + cg * 4];
            float4 o4 = make_float4(tf32r(v.x), tf32r(v.y), tf32r(v.z), tf32r(v.w));
            *(float4*)&Xs[row * 36 + cg * 4] = o4;
        }
        // W tile: 32x64 (512 float4)
        #pragma unroll
        for (int i = 0; i < 2; i++) {
            int fi = i * 256 + tid;
            int row = fi >> 4, cg = fi & 15;
            float4 v = *(const float4*)&W[(k0 + row) * D_ + c0 + cg * 4];
            float4 o4 = make_float4(tf32r(v.x), tf32r(v.y), tf32r(v.z), tf32r(v.w));
            *(float4*)&Ws[row * 72 + cg * 4] = o4;
        }
        __syncthreads();

        #pragma unroll
        for (int kk = 0; kk < 4; kk++) {
            float a[4];
            a[0] = Xs[(w * 16 + g)     * 36 + kk * 8 + t];
            a[1] = Xs[(w * 16 + g + 8) * 36 + kk * 8 + t];
            a[2] = Xs[(w * 16 + g)     * 36 + kk * 8 + t + 4];
            a[3] = Xs[(w * 16 + g + 8) * 36 + kk * 8 + t + 4];
            #pragma unroll
            for (int j = 0; j < 8; j++) {
                float bf[2];
                bf[0] = Ws[(kk * 8 + t)     * 72 + j * 8 + g];
                bf[1] = Ws[(kk * 8 + t + 4) * 72 + j * 8 + g];
                mma8(c[j], a, bf);
            }
        }
    }

    // Epilogue: add bias, scatter to [b, h, n, p]
    const int h = blockIdx.x;   // c0 / 64
    #pragma unroll
    for (int j = 0; j < 8; j++) {
        int pcol = j * 8 + t * 2;
        float2 bb = *(const float2*)&bias[c0 + pcol];
        int r = r0 + w * 16 + g;
        int bi = r >> 12, n = r & (N_ - 1);
        float2 o0 = make_float2(c[j][0] + bb.x, c[j][1] + bb.y);
        *(float2*)&out[(((bi * H_ + h) * N_) + n) * P_ + pcol] = o0;
        r += 8; bi = r >> 12; n = r & (N_ - 1);
        float2 o1 = make_float2(c[j][2] + bb.x, c[j][3] + bb.y);
        *(float2*)&out[(((bi * H_ + h) * N_) + n) * P_ + pcol] = o1;
    }
}

// ---------------------------------------------------------------------------
// Flash attention (tf32 MMA): CTA = (b, h, 128 query rows). KV tile = 64.
// 8 warps, each owns 16 query rows x full 64 cols -> softmax is intra-warp.
// Strides: Qs/Ks/Ps = 68, Vs = 72 (per-fragment conflict-free).
// ---------------------------------------------------------------------------
__global__ __launch_bounds__(256, 2) void attn_kernel(float* __restrict__ out)
{
    extern __shared__ float smem[];
    float* Qs = smem;                    // [128][68]
    float* Ks = Qs + 128 * 68;           // [64][68]
    float* Vs = Ks + 64 * 68;            // [64][72]
    float* Ps = Vs + 64 * 72;            // [128][68]

    const int tid = threadIdx.x;
    const int w = tid >> 5, lane = tid & 31;
    const int g = lane >> 2, t = lane & 3;
    const int b = blockIdx.z, h = blockIdx.y;
    const int n0 = blockIdx.x * 128;
    const int qrow = w * 16;

    const float* Qg = g_Q + ((b * H_ + h) * N_ + n0) * P_;
    const float* Kg = g_K + (b * H_ + h) * (M_ * P_);
    const float* Vg = g_V + (b * H_ + h) * (M_ * P_);

    // Stage Q (tf32-rounded): 128x64 = 2048 float4
    #pragma unroll
    for (int i = 0; i < 8; i++) {
        int fi = i * 256 + tid;
        int row = fi >> 4, cg = fi & 15;
        float4 v = *(const float4*)&Qg[row * P_ + cg * 4];
        float4 o4 = make_float4(tf32r(v.x), tf32r(v.y), tf32r(v.z), tf32r(v.w));
        *(float4*)&Qs[row * 68 + cg * 4] = o4;
    }

    float m0 = -INFINITY, m1 = -INFINITY, l0 = 0.f, l1 = 0.f;
    float o[8][4];
    #pragma unroll
    for (int j = 0; j < 8; j++)
        #pragma unroll
        for (int e = 0; e < 4; e++) o[j][e] = 0.f;

    for (int tile = 0; tile < M_ / 64; tile++) {
        __syncthreads();   // previous iteration's Ks/Vs reads complete
        const float* Kt = Kg + tile * 64 * P_;
        const float* Vt = Vg + tile * 64 * P_;
        #pragma unroll
        for (int i = 0; i < 4; i++) {
            int fi = i * 256 + tid;
            int row = fi >> 4, cg = fi & 15;
            float4 kv = *(const float4*)&Kt[row * P_ + cg * 4];
            *(float4*)&Ks[row * 68 + cg * 4] =
                make_float4(tf32r(kv.x), tf32r(kv.y), tf32r(kv.z), tf32r(kv.w));
            float4 vv = *(const float4*)&Vt[row * P_ + cg * 4];
            *(float4*)&Vs[row * 72 + cg * 4] =
                make_float4(tf32r(vv.x), tf32r(vv.y), tf32r(vv.z), tf32r(vv.w));
        }
        __syncthreads();

        // ---- S = Q @ K^T (warp: 16 rows x 64 cols) ----
        float s[8][4];
        #pragma unroll
        for (int j = 0; j < 8; j++)
            #pragma unroll
            for (int e = 0; e < 4; e++) s[j][e] = 0.f;

        #pragma unroll
        for (int kk = 0; kk < 8; kk++) {
            float a[4];
            a[0] = Qs[(qrow + g)     * 68 + kk * 8 + t];
            a[1] = Qs[(qrow + g + 8) * 68 + kk * 8 + t];
            a[2] = Qs[(qrow + g)     * 68 + kk * 8 + t + 4];
            a[3] = Qs[(qrow + g + 8) * 68 + kk * 8 + t + 4];
            #pragma unroll
            for (int j = 0; j < 8; j++) {
                float bf[2];
                bf[0] = Ks[(j * 8 + g) * 68 + kk * 8 + t];
                bf[1] = Ks[(j * 8 + g) * 68 + kk * 8 + t + 4];
                mma8(s[j], a, bf);
            }
        }
        #pragma unroll
        for (int j = 0; j < 8; j++)
            #pragma unroll
            for (int e = 0; e < 4; e++) s[j][e] *= 0.125f;   // 1/sqrt(64)

        // ---- online softmax (rows g and g+8; reduce over 4 lanes of group) ----
        float rmax0 = -INFINITY, rmax1 = -INFINITY;
        #pragma unroll
        for (int j = 0; j < 8; j++) {
            rmax0 = fmaxf(rmax0, fmaxf(s[j][0], s[j][1]));
            rmax1 = fmaxf(rmax1, fmaxf(s[j][2], s[j][3]));
        }
        #pragma unroll
        for (int off = 1; off <= 2; off <<= 1) {
            rmax0 = fmaxf(rmax0, __shfl_xor_sync(0xffffffffu, rmax0, off));
            rmax1 = fmaxf(rmax1, __shfl_xor_sync(0xffffffffu, rmax1, off));
        }
        float mn0 = fmaxf(m0, rmax0), mn1 = fmaxf(m1, rmax1);
        float alpha0 = __expf(m0 - mn0), alpha1 = __expf(m1 - mn1);
        m0 = mn0; m1 = mn1;

        float rs0 = 0.f, rs1 = 0.f;
        #pragma unroll
        for (int j = 0; j < 8; j++) {
            s[j][0] = __expf(s[j][0] - m0); rs0 += s[j][0];
            s[j][1] = __expf(s[j][1] - m0); rs0 += s[j][1];
            s[j][2] = __expf(s[j][2] - m1); rs1 += s[j][2];
            s[j][3] = __expf(s[j][3] - m1); rs1 += s[j][3];
        }
        #pragma unroll
        for (int off = 1; off <= 2; off <<= 1) {
            rs0 += __shfl_xor_sync(0xffffffffu, rs0, off);
            rs1 += __shfl_xor_sync(0xffffffffu, rs1, off);
        }
        l0 = l0 * alpha0 + rs0;
        l1 = l1 * alpha1 + rs1;
        #pragma unroll
        for (int j = 0; j < 8; j++) {
            o[j][0] *= alpha0; o[j][1] *= alpha0;
            o[j][2] *= alpha1; o[j][3] *= alpha1;
        }

        // ---- stage P (intra-warp only: warp owns its 16 rows fully) ----
        #pragma unroll
        for (int j = 0; j < 8; j++) {
            *(float2*)&Ps[(qrow + g)     * 68 + j * 8 + t * 2] =
                make_float2(tf32r(s[j][0]), tf32r(s[j][1]));
            *(float2*)&Ps[(qrow + g + 8) * 68 + j * 8 + t * 2] =
                make_float2(tf32r(s[j][2]), tf32r(s[j][3]));
        }
        __syncwarp();

        // ---- O += P @ V ----
        #pragma unroll
        for (int kk = 0; kk < 8; kk++) {
            float a[4];
            a[0] = Ps[(qrow + g)     * 68 + kk * 8 + t];
            a[1] = Ps[(qrow + g + 8) * 68 + kk * 8 + t];
            a[2] = Ps[(qrow + g)     * 68 + kk * 8 + t + 4];
            a[3] = Ps[(qrow + g + 8) * 68 + kk * 8 + t + 4];
            #pragma unroll
            for (int j = 0; j < 8; j++) {
                float bf[2];
                bf[0] = Vs[(kk * 8 + t)     * 72 + j * 8 + g];
                bf[1] = Vs[(kk * 8 + t + 4) * 72 + j * 8 + g];
                mma8(o[j], a, bf);
            }
        }
        __syncwarp();
    }

    // ---- epilogue: normalize, store [B, N, D] ----
    float inv0 = 1.f / l0, inv1 = 1.f / l1;
    #pragma unroll
    for (int j = 0; j < 8; j++) {
        int pcol = j * 8 + t * 2;
        int n = n0 + qrow + g;
        *(float2*)&out[(size_t)(b * N_ + n) * D_ + h * 64 + pcol] =
            make_float2(o[j][0] * inv0, o[j][1] * inv0);
        n += 8;
        *(float2*)&out[(size_t)(b * N_ + n) * D_ + h * 64 + pcol] =
            make_float2(o[j][2] * inv1, o[j][3] * inv1);
    }
}

// ---------------------------------------------------------------------------
extern "C" void kernel_launch(void* const* d_in, const int* in_sizes, int n_in,
                              void* d_out, int out_size)
{
    const float* xq = (const float*)d_in[0];
    const float* xk = (const float*)d_in[1];
    const float* xv = (const float*)d_in[2];
    const float* Wq = (const float*)d_in[3];
    const float* bq = (const float*)d_in[4];
    const float* Wk = (const float*)d_in[5];
    const float* bk = (const float*)d_in[6];
    const float* Wv = (const float*)d_in[7];
    const float* bv = (const float*)d_in[8];
    float* out = (float*)d_out;

    const int attn_smem = (128 * 68 + 64 * 68 + 64 * 72 + 128 * 68) * (int)sizeof(float); // 105472
    cudaFuncSetAttribute(attn_kernel, cudaFuncAttributeMaxDynamicSharedMemorySize, attn_smem);

    proj_kernel<<<dim3(D_ / 64, (B_ * N_) / 128, 3), 256>>>(xq, xk, xv, Wq, Wk, Wv, bq, bk, bv);
    attn_kernel<<<dim3(N_ / 128, H_, B_), 256, attn_smem>>>(out);
}